// round 5
// baseline (speedup 1.0000x reference)
#include <cuda_runtime.h>
#include <math.h>

#define TT 100
#define BB 64
#define II 256
#define HH 512
#define H3 1536
#define H4 2048
#define NBLK 128          // persistent grid size (<=148 SMs, 1 block/SM)
#define KC 16             // K split chunks (512/32)
#define BKC 32            // K per chunk

// ---------------- scratch (device globals) ----------------
__device__ float g_WihP[II * H4];                 // packed: [k][ (n%512)*4 + n/512 ]
__device__ float g_WhhP[HH * H4];
__device__ float g_biasP[H4];
__device__ float g_Gx[(size_t)TT * BB * H4];      // packed gate pre-activations from input path
__device__ float g_h[(size_t)(TT + 1) * BB * HH]; // h history (standard [b][h] layout per t)
__device__ float g_c[BB * HH];
__device__ float g_f[(size_t)TT * BB * HH];
__device__ float g_d[(size_t)TT * BB * H3];       // later overwritten with w = d * suffix-prod(f)
__device__ float g_gpart[(size_t)KC * BB * H4];   // split-K partials, packed cols
__device__ unsigned g_bar;                        // grid barrier counter (monotonic per launch)

// ---------------- prep ----------------
__global__ void prep_kernel(const float* __restrict__ h0, const float* __restrict__ c0,
                            const float* __restrict__ bih, const float* __restrict__ bhh) {
    int i = blockIdx.x * blockDim.x + threadIdx.x;
    if (i == 0) g_bar = 0u;
    if (i < H4) g_biasP[i >= 0 ? ((i & 511) * 4 + (i >> 9)) : 0] = bih[i] + bhh[i];
    if (i < BB * HH) { g_h[i] = h0[i]; g_c[i] = c0[i]; }
}

// ---------------- pack weights: in[2048][K] -> out[K][2048 packed] ----------------
__global__ void pack_w(const float* __restrict__ in, int K, int which) {
    __shared__ float s[32][33];
    int k0 = blockIdx.x * 32, n0 = blockIdx.y * 32;
    int tx = threadIdx.x, ty = threadIdx.y;
    for (int i = ty; i < 32; i += 8)
        s[i][tx] = in[(size_t)(n0 + i) * K + k0 + tx];
    __syncthreads();
    float* out = which ? g_WhhP : g_WihP;
    int g = n0 >> 9;            // gate index (n0 is 32-aligned, 512 | 32)
    int c = n0 & 511;
    for (int i = ty; i < 32; i += 8)
        out[(size_t)(k0 + i) * H4 + (c + tx) * 4 + g] = s[tx][i];
}

// ---------------- Gx = X[6400,256] @ WihP[256,2048] + biasP (packed out) ----------------
// 128x128 tile, 256 threads, 8x8 microtile, BK=8
__global__ void gx_kernel(const float* __restrict__ X) {
    __shared__ __align__(16) float As[8][132];
    __shared__ __align__(16) float Bs[8][128];
    const int tid = threadIdx.x;
    const int n0 = blockIdx.x * 128;     // 16 tiles
    const int m0 = blockIdx.y * 128;     // 50 tiles
    const int tm = (tid >> 4) * 8, tn = (tid & 15) * 8;
    const int am = tid >> 1, ak = (tid & 1) * 4;
    const int bk = tid >> 5, bn = (tid & 31) * 4;
    float acc[8][8] = {};
    for (int k0 = 0; k0 < II; k0 += 8) {
        float4 av = *(const float4*)(X + (size_t)(m0 + am) * II + k0 + ak);
        As[ak + 0][am] = av.x; As[ak + 1][am] = av.y; As[ak + 2][am] = av.z; As[ak + 3][am] = av.w;
        *(float4*)&Bs[bk][bn] = *(const float4*)(g_WihP + (size_t)(k0 + bk) * H4 + n0 + bn);
        __syncthreads();
#pragma unroll
        for (int u = 0; u < 8; u++) {
            float4 a0 = *(const float4*)&As[u][tm];
            float4 a1 = *(const float4*)&As[u][tm + 4];
            float4 b0 = *(const float4*)&Bs[u][tn];
            float4 b1 = *(const float4*)&Bs[u][tn + 4];
            float aa[8] = {a0.x, a0.y, a0.z, a0.w, a1.x, a1.y, a1.z, a1.w};
            float bb[8] = {b0.x, b0.y, b0.z, b0.w, b1.x, b1.y, b1.z, b1.w};
#pragma unroll
            for (int i = 0; i < 8; i++)
#pragma unroll
                for (int j = 0; j < 8; j++)
                    acc[i][j] += aa[i] * bb[j];
        }
        __syncthreads();
    }
#pragma unroll
    for (int i = 0; i < 8; i++) {
        float* orow = g_Gx + (size_t)(m0 + tm + i) * H4 + n0 + tn;
        float4 v0 = make_float4(acc[i][0] + g_biasP[n0 + tn + 0], acc[i][1] + g_biasP[n0 + tn + 1],
                                acc[i][2] + g_biasP[n0 + tn + 2], acc[i][3] + g_biasP[n0 + tn + 3]);
        float4 v1 = make_float4(acc[i][4] + g_biasP[n0 + tn + 4], acc[i][5] + g_biasP[n0 + tn + 5],
                                acc[i][6] + g_biasP[n0 + tn + 6], acc[i][7] + g_biasP[n0 + tn + 7]);
        *(float4*)orow = v0;
        *(float4*)(orow + 4) = v1;
    }
}

// ---------------- grid barrier (monotonic counter; reset by prep each launch) ----------------
__device__ __forceinline__ void gbar(unsigned& target) {
    __syncthreads();
    if (threadIdx.x == 0) {
        __threadfence();
        atomicAdd(&g_bar, 1u);
        target += NBLK;
        while (atomicAdd(&g_bar, 0u) < target) __nanosleep(64);
        __threadfence();
    }
    __syncthreads();
}

// ---------------- persistent recurrent loop ----------------
// 128 blocks x 256 threads. Block (n-tile, k-chunk): n-tile 0..7 (256 packed cols),
// k-chunk 0..15 (32 K each). Weights chunk cached in smem for all 100 steps.
__global__ void __launch_bounds__(256, 1)
loop_kernel(float* __restrict__ out_h, float* __restrict__ out_c) {
    __shared__ __align__(16) float Bs[BKC][256];   // weight chunk [k][n] packed (32KB)
    __shared__ __align__(16) float As[BKC][68];    // h chunk [k][m]
    const int tid = threadIdx.x;
    const int nt = blockIdx.x & 7;         // n-tile
    const int kc = blockIdx.x >> 3;        // k-chunk
    const int n0 = nt * 256;
    const int k0 = kc * BKC;

    // load weight chunk once (8192 floats / 256 threads = 32 each)
    {
        const float* wsrc = g_WhhP + (size_t)k0 * H4 + n0;
#pragma unroll
        for (int r = 0; r < 8; r++) {
            int e = r * 256 + tid;             // 0..2047 -> (k, n/4)
            int kk = e >> 6;                   // 64 float4 per row
            int nn = (e & 63) * 4;
            *(float4*)&Bs[kk][nn] = *(const float4*)(wsrc + (size_t)kk * H4 + nn);
        }
    }

    const int tm = (tid >> 4) * 8, tn = (tid & 15) * 8;   // 8x8 microtile over 64x128... (64m x 128n half? no: 16x16 grid covers 128m? we have M=64)
    // NOTE: tile is M=64 x N=256. thread grid: 8 (m-groups) x 32 (n-groups): 
    const int ttm = (tid >> 5) * 8;          // 8 groups * 8 = 64 m
    const int ttn = (tid & 31) * 8;          // 32 groups * 8 = 256 n
    const int am = tid >> 2, ak = (tid & 3) * 8;  // A load map: 64 m x 8 k-quads

    const int cell = blockIdx.x * 256 + tid;  // 0..32767
    const int cb = cell >> 9, ch = cell & 511;

    unsigned target = 0;

    for (int t = 0; t < TT; t++) {
        // ---- load A chunk: h_t[64][k0..k0+31] -> As[k][m] ----
        const float* hsrc = g_h + (size_t)t * BB * HH;
        float4 v0 = __ldcg((const float4*)(hsrc + (size_t)am * HH + k0 + ak));
        float4 v1 = __ldcg((const float4*)(hsrc + (size_t)am * HH + k0 + ak + 4));
        As[ak + 0][am] = v0.x; As[ak + 1][am] = v0.y; As[ak + 2][am] = v0.z; As[ak + 3][am] = v0.w;
        As[ak + 4][am] = v1.x; As[ak + 5][am] = v1.y; As[ak + 6][am] = v1.z; As[ak + 7][am] = v1.w;
        __syncthreads();

        // ---- GEMM: 64x256 tile, K=32 ----
        float acc[8][8] = {};
#pragma unroll
        for (int u = 0; u < BKC; u++) {
            float4 a0 = *(const float4*)&As[u][ttm];
            float4 a1 = *(const float4*)&As[u][ttm + 4];
            float4 b0 = *(const float4*)&Bs[u][ttn];
            float4 b1 = *(const float4*)&Bs[u][ttn + 4];
            float aa[8] = {a0.x, a0.y, a0.z, a0.w, a1.x, a1.y, a1.z, a1.w};
            float bb[8] = {b0.x, b0.y, b0.z, b0.w, b1.x, b1.y, b1.z, b1.w};
#pragma unroll
            for (int i = 0; i < 8; i++)
#pragma unroll
                for (int j = 0; j < 8; j++)
                    acc[i][j] += aa[i] * bb[j];
        }
        // write partials (packed cols)
#pragma unroll
        for (int i = 0; i < 8; i++) {
            float* prow = g_gpart + ((size_t)kc * BB + ttm + i) * H4 + n0 + ttn;
            *(float4*)prow = make_float4(acc[i][0], acc[i][1], acc[i][2], acc[i][3]);
            *(float4*)(prow + 4) = make_float4(acc[i][4], acc[i][5], acc[i][6], acc[i][7]);
        }
        __syncthreads();   // As reused next step; also pre-barrier ordering
        gbar(target);

        // ---- cell: one element per thread ----
        {
            float4 g4 = __ldcg((const float4*)(g_Gx + ((size_t)t * BB + cb) * H4 + 4 * ch));
#pragma unroll
            for (int q = 0; q < KC; q++) {
                float4 p = __ldcg((const float4*)(g_gpart + ((size_t)q * BB + cb) * H4 + 4 * ch));
                g4.x += p.x; g4.y += p.y; g4.z += p.z; g4.w += p.w;
            }
            float i = 1.f / (1.f + expf(-g4.x));
            float f = 1.f / (1.f + expf(-g4.y));
            float g = tanhf(g4.z);
            float o = 1.f / (1.f + expf(-g4.w));
            float cx = g_c[cell];
            float cy = f * cx + i * g;
            float hy = o * tanhf(cy);
            g_c[cell] = cy;
            g_h[(size_t)(t + 1) * BB * HH + cell] = hy;
            out_h[(size_t)t * BB * HH + cell] = hy;
            g_f[(size_t)t * BB * HH + cell] = f;
            size_t db = (size_t)t * BB * H3 + (size_t)cb * H3 + ch;
            g_d[db]          = g * i * (1.f - i);
            g_d[db + HH]     = cx * f * (1.f - f);
            g_d[db + 2 * HH] = i * (1.f - g) * (1.f + g);
            if (t == TT - 1) out_c[cell] = cy;
        }
        gbar(target);
    }
    (void)tm; (void)tn;
}

// ---------------- reverse suffix-product scan ----------------
__global__ void scan_kernel(float* __restrict__ evb_out) {
    int idx = blockIdx.x * blockDim.x + threadIdx.x;  // < BB*H3
    int b = idx / H3, j = idx % H3;
    int h = j & (HH - 1);
    float p = 1.f, sum = 0.f;
    for (int t = TT - 1; t >= 0; t--) {
        size_t di = (size_t)t * BB * H3 + (size_t)b * H3 + j;
        float w = g_d[di] * p;
        g_d[di] = w;
        sum += w;
        p *= g_f[(size_t)t * BB * HH + (size_t)b * HH + h];
    }
    evb_out[idx] = sum;
}

// ---------------- batched ev GEMM: out[b][j][k] = sum_t w[t][b][j] * Xs[t][b][k] ----------------
__global__ void ev_kernel(const float* __restrict__ Xs, int kdim, float* __restrict__ out) {
    __shared__ __align__(16) float Ws[8][128];
    __shared__ __align__(16) float Bs[8][128];
    if (Xs == nullptr) Xs = g_h;  // ev_hh: h_{t-1} history
    const int tid = threadIdx.x;
    const int b = blockIdx.z;
    const int j0 = blockIdx.y * 128;
    const int k0 = blockIdx.x * 128;
    const int tj = (tid >> 4) * 8, tk = (tid & 15) * 8;
    const int ltt = tid >> 5;
    const int lj = (tid & 31) * 4;
    float acc[8][8] = {};
    for (int t0 = 0; t0 < TT; t0 += 8) {
        int t = t0 + ltt;
        float4 wv = make_float4(0.f, 0.f, 0.f, 0.f);
        float4 xv = make_float4(0.f, 0.f, 0.f, 0.f);
        if (t < TT) {
            wv = *(const float4*)(g_d + (size_t)t * BB * H3 + (size_t)b * H3 + j0 + lj);
            xv = *(const float4*)(Xs + ((size_t)t * BB + b) * kdim + k0 + lj);
        }
        *(float4*)&Ws[ltt][lj] = wv;
        *(float4*)&Bs[ltt][lj] = xv;
        __syncthreads();
#pragma unroll
        for (int u = 0; u < 8; u++) {
            float4 a0 = *(const float4*)&Ws[u][tj];
            float4 a1 = *(const float4*)&Ws[u][tj + 4];
            float4 b0 = *(const float4*)&Bs[u][tk];
            float4 b1 = *(const float4*)&Bs[u][tk + 4];
            float aa[8] = {a0.x, a0.y, a0.z, a0.w, a1.x, a1.y, a1.z, a1.w};
            float bb[8] = {b0.x, b0.y, b0.z, b0.w, b1.x, b1.y, b1.z, b1.w};
#pragma unroll
            for (int i = 0; i < 8; i++)
#pragma unroll
                for (int j = 0; j < 8; j++)
                    acc[i][j] += aa[i] * bb[j];
        }
        __syncthreads();
    }
#pragma unroll
    for (int i = 0; i < 8; i++) {
        float* orow = out + ((size_t)b * H3 + j0 + tj + i) * kdim + k0 + tk;
        *(float4*)orow = make_float4(acc[i][0], acc[i][1], acc[i][2], acc[i][3]);
        *(float4*)(orow + 4) = make_float4(acc[i][4], acc[i][5], acc[i][6], acc[i][7]);
    }
}

// ---------------- launch ----------------
extern "C" void kernel_launch(void* const* d_in, const int* in_sizes, int n_in,
                              void* d_out, int out_size) {
    (void)in_sizes; (void)n_in; (void)out_size;
    const float* input = (const float*)d_in[0];
    const float* h0    = (const float*)d_in[1];
    const float* c0    = (const float*)d_in[2];
    const float* wih   = (const float*)d_in[3];
    const float* whh   = (const float*)d_in[4];
    const float* bih   = (const float*)d_in[5];
    const float* bhh   = (const float*)d_in[6];

    float* out         = (float*)d_out;
    float* out_outputs = out;
    float* out_cx      = out_outputs + (size_t)TT * BB * HH;
    float* out_evih    = out_cx + (size_t)BB * HH;
    float* out_evhh    = out_evih + (size_t)BB * H3 * II;
    float* out_evb     = out_evhh + (size_t)BB * H3 * HH;

    prep_kernel<<<512, 256>>>(h0, c0, bih, bhh);
    pack_w<<<dim3(II / 32, H4 / 32), dim3(32, 8)>>>(wih, II, 0);
    pack_w<<<dim3(HH / 32, H4 / 32), dim3(32, 8)>>>(whh, HH, 1);
    gx_kernel<<<dim3(16, 50), 256>>>(input);

    loop_kernel<<<NBLK, 256>>>(out_outputs, out_cx);

    scan_kernel<<<BB * H3 / 256, 256>>>(out_evb);
    ev_kernel<<<dim3(II / 128, H3 / 128, BB), 256>>>(input, II, out_evih);
    ev_kernel<<<dim3(HH / 128, H3 / 128, BB), 256>>>(nullptr, HH, out_evhh);
}

// round 6
// speedup vs baseline: 1.0810x; 1.0810x over previous
#include <cuda_runtime.h>
#include <math.h>

#define TT 100
#define BB 64
#define II 256
#define HH 512
#define H3 1536
#define H4 2048
#define NBLK 128          // persistent grid size (all co-resident)
#define KC 16             // K split chunks across blocks (512/32)
#define BKC 32            // K per chunk

// B-tile float4-index permutation: spreads lane-stride-8-word reads over all banks
#define PF4(x) ((x) + ((x) >> 3))

// ---------------- scratch (device globals) ----------------
__device__ float g_WihP[II * H4];                 // packed: [k][ (n%512)*4 + n/512 ]
__device__ float g_WhhP[HH * H4];
__device__ float g_biasP[H4];
__device__ float g_Gx[(size_t)TT * BB * H4];      // packed gate pre-activations from input path
__device__ float g_h[(size_t)(TT + 1) * BB * HH]; // h history [t][b][h]
__device__ float g_f[(size_t)TT * BB * HH];
__device__ float g_d[(size_t)TT * BB * H3];       // later overwritten with w = d * suffix-prod(f)
__device__ float g_gpart[(size_t)KC * BB * H4];   // split-K partials, packed cols
__device__ unsigned g_cnt_g[TT][8];               // partials-done counters per (t, nt)
__device__ unsigned g_cnt_c[TT][8];               // cells-done counters per (t, nt)

// ---------------- prep ----------------
__global__ void prep_kernel(const float* __restrict__ h0, const float* __restrict__ bih,
                            const float* __restrict__ bhh) {
    int i = blockIdx.x * blockDim.x + threadIdx.x;
    if (i < TT * 8) { (&g_cnt_g[0][0])[i] = 0u; (&g_cnt_c[0][0])[i] = 0u; }
    if (i < H4) g_biasP[(i & 511) * 4 + (i >> 9)] = bih[i] + bhh[i];
    if (i < BB * HH) g_h[i] = h0[i];
}

// ---------------- pack weights: in[2048][K] -> out[K][2048 packed] ----------------
__global__ void pack_w(const float* __restrict__ in, int K, int which) {
    __shared__ float s[32][33];
    int k0 = blockIdx.x * 32, n0 = blockIdx.y * 32;
    int tx = threadIdx.x, ty = threadIdx.y;
    for (int i = ty; i < 32; i += 8)
        s[i][tx] = in[(size_t)(n0 + i) * K + k0 + tx];
    __syncthreads();
    float* out = which ? g_WhhP : g_WihP;
    int g = n0 >> 9;
    int c = n0 & 511;
    for (int i = ty; i < 32; i += 8)
        out[(size_t)(k0 + i) * H4 + (c + tx) * 4 + g] = s[tx][i];
}

// ---------------- Gx = X[6400,256] @ WihP[256,2048] + biasP (packed out) ----------------
// 128x128 tile, 256 threads, 8x8 microtile, BK=8. B-tile swizzled via PF4.
__global__ void gx_kernel(const float* __restrict__ X) {
    __shared__ __align__(16) float As[8][132];
    __shared__ __align__(16) float Bs[8][140];    // 35 f4 slots (PF4 max 34)
    const int tid = threadIdx.x;
    const int n0 = blockIdx.x * 128;
    const int m0 = blockIdx.y * 128;
    const int tm = (tid >> 4) * 8, tn = (tid & 15) * 8;
    const int am = tid >> 1, ak = (tid & 1) * 4;
    const int bk = tid >> 5, bn_f4 = tid & 31;    // write f4 index
    const int pn0 = PF4((tn >> 2));               // read f4 indices (precomputed)
    const int pn1 = PF4((tn >> 2) + 1);
    float acc[8][8] = {};
    for (int k0 = 0; k0 < II; k0 += 8) {
        float4 av = *(const float4*)(X + (size_t)(m0 + am) * II + k0 + ak);
        As[ak + 0][am] = av.x; As[ak + 1][am] = av.y; As[ak + 2][am] = av.z; As[ak + 3][am] = av.w;
        ((float4*)&Bs[bk][0])[PF4(bn_f4)] = *(const float4*)(g_WihP + (size_t)(k0 + bk) * H4 + n0 + bn_f4 * 4);
        __syncthreads();
#pragma unroll
        for (int u = 0; u < 8; u++) {
            float4 a0 = *(const float4*)&As[u][tm];
            float4 a1 = *(const float4*)&As[u][tm + 4];
            float4 b0 = ((const float4*)&Bs[u][0])[pn0];
            float4 b1 = ((const float4*)&Bs[u][0])[pn1];
            float aa[8] = {a0.x, a0.y, a0.z, a0.w, a1.x, a1.y, a1.z, a1.w};
            float bb[8] = {b0.x, b0.y, b0.z, b0.w, b1.x, b1.y, b1.z, b1.w};
#pragma unroll
            for (int i = 0; i < 8; i++)
#pragma unroll
                for (int j = 0; j < 8; j++)
                    acc[i][j] += aa[i] * bb[j];
        }
        __syncthreads();
    }
#pragma unroll
    for (int i = 0; i < 8; i++) {
        float* orow = g_Gx + (size_t)(m0 + tm + i) * H4 + n0 + tn;
        float4 v0 = make_float4(acc[i][0] + g_biasP[n0 + tn + 0], acc[i][1] + g_biasP[n0 + tn + 1],
                                acc[i][2] + g_biasP[n0 + tn + 2], acc[i][3] + g_biasP[n0 + tn + 3]);
        float4 v1 = make_float4(acc[i][4] + g_biasP[n0 + tn + 4], acc[i][5] + g_biasP[n0 + tn + 5],
                                acc[i][6] + g_biasP[n0 + tn + 6], acc[i][7] + g_biasP[n0 + tn + 7]);
        *(float4*)orow = v0;
        *(float4*)(orow + 4) = v1;
    }
}

// ---------------- persistent recurrent loop: flag-pipelined, no grid barrier ----------------
// 128 blocks x 256 threads. Block (nt 0..7, kc 0..15): GEMM tile M=64,N=256(packed),K=32.
// Cell: block handles b in [kc*4, kc*4+4) x h-cols [nt*64, nt*64+64); c state in register.
__global__ void __launch_bounds__(256, 1)
loop_kernel(const float* __restrict__ c0, float* __restrict__ out_h, float* __restrict__ out_c) {
    __shared__ __align__(16) float Bs[BKC][284];   // 71 f4 slots (PF4 max 70), ~36.4KB
    __shared__ __align__(16) float As[BKC][68];
    const int tid = threadIdx.x;
    const int nt = blockIdx.x & 7;
    const int kc = blockIdx.x >> 3;
    const int n0 = nt * 256;
    const int k0 = kc * BKC;

    // stage weight chunk once (swizzled)
    {
        const float* wsrc = g_WhhP + (size_t)k0 * H4 + n0;
#pragma unroll
        for (int r = 0; r < 8; r++) {
            int e = r * 256 + tid;
            int kk = e >> 6;
            int nf4 = e & 63;
            ((float4*)&Bs[kk][0])[PF4(nf4)] = *(const float4*)(wsrc + (size_t)kk * H4 + nf4 * 4);
        }
    }

    const int ttm = (tid >> 5) * 8;          // warp-uniform m (broadcast A reads)
    const int ttn = (tid & 31) * 8;
    const int pn0 = PF4(ttn >> 2);
    const int pn1 = PF4((ttn >> 2) + 1);
    const int am = tid >> 2, ak = (tid & 3) * 8;

    // cell identity (fixed all steps): b in this block's b-slice, one h-col
    const int cb = kc * 4 + (tid >> 6);      // batch
    const int chl = tid & 63;                // local h col
    const int ch = nt * 64 + chl;            // global h col
    float creg = c0[(size_t)cb * HH + ch];

    const int nt_src = kc >> 1;              // producer nt of this block's A k-chunk

    for (int t = 0; t < TT; t++) {
        // ---- wait for h[t] producers (skip t=0: prep wrote it) ----
        if (t > 0) {
            if (tid == 0) {
                while (atomicAdd(&g_cnt_c[t - 1][nt_src], 0u) < 16u) __nanosleep(64);
                __threadfence();
            }
            __syncthreads();
        }

        // ---- load A chunk: h[t][64][k0..k0+32) -> As[k][m] ----
        const float* hsrc = g_h + (size_t)t * BB * HH;
        float4 v0 = __ldcg((const float4*)(hsrc + (size_t)am * HH + k0 + ak));
        float4 v1 = __ldcg((const float4*)(hsrc + (size_t)am * HH + k0 + ak + 4));
        As[ak + 0][am] = v0.x; As[ak + 1][am] = v0.y; As[ak + 2][am] = v0.z; As[ak + 3][am] = v0.w;
        As[ak + 4][am] = v1.x; As[ak + 5][am] = v1.y; As[ak + 6][am] = v1.z; As[ak + 7][am] = v1.w;
        __syncthreads();

        // ---- GEMM 64x256, K=32 ----
        float acc[8][8] = {};
#pragma unroll
        for (int u = 0; u < BKC; u++) {
            float4 a0 = *(const float4*)&As[u][ttm];
            float4 a1 = *(const float4*)&As[u][ttm + 4];
            float4 b0 = ((const float4*)&Bs[u][0])[pn0];
            float4 b1 = ((const float4*)&Bs[u][0])[pn1];
            float aa[8] = {a0.x, a0.y, a0.z, a0.w, a1.x, a1.y, a1.z, a1.w};
            float bb[8] = {b0.x, b0.y, b0.z, b0.w, b1.x, b1.y, b1.z, b1.w};
#pragma unroll
            for (int i = 0; i < 8; i++)
#pragma unroll
                for (int j = 0; j < 8; j++)
                    acc[i][j] += aa[i] * bb[j];
        }
#pragma unroll
        for (int i = 0; i < 8; i++) {
            float* prow = g_gpart + ((size_t)kc * BB + ttm + i) * H4 + n0 + ttn;
            *(float4*)prow = make_float4(acc[i][0], acc[i][1], acc[i][2], acc[i][3]);
            *(float4*)(prow + 4) = make_float4(acc[i][4], acc[i][5], acc[i][6], acc[i][7]);
        }

        // ---- signal partials done, wait for all 16 kc partials of our nt ----
        __threadfence();
        __syncthreads();                      // As also reused next step
        if (tid == 0) {
            atomicAdd(&g_cnt_g[t][nt], 1u);
            while (atomicAdd(&g_cnt_g[t][nt], 0u) < 16u) __nanosleep(64);
            __threadfence();
        }
        __syncthreads();

        // ---- cell for (cb, ch) ----
        {
            float4 g4 = __ldcg((const float4*)(g_Gx + ((size_t)t * BB + cb) * H4 + 4 * ch));
#pragma unroll
            for (int q = 0; q < KC; q++) {
                float4 p = __ldcg((const float4*)(g_gpart + ((size_t)q * BB + cb) * H4 + 4 * ch));
                g4.x += p.x; g4.y += p.y; g4.z += p.z; g4.w += p.w;
            }
            float i = 1.f / (1.f + expf(-g4.x));
            float f = 1.f / (1.f + expf(-g4.y));
            float g = tanhf(g4.z);
            float o = 1.f / (1.f + expf(-g4.w));
            float cx = creg;
            float cy = f * cx + i * g;
            float hy = o * tanhf(cy);
            creg = cy;
            size_t hb = (size_t)cb * HH + ch;
            g_h[(size_t)(t + 1) * BB * HH + hb] = hy;
            out_h[(size_t)t * BB * HH + hb] = hy;
            g_f[(size_t)t * BB * HH + hb] = f;
            size_t db = (size_t)t * BB * H3 + (size_t)cb * H3 + ch;
            g_d[db]          = g * i * (1.f - i);
            g_d[db + HH]     = cx * f * (1.f - f);
            g_d[db + 2 * HH] = i * (1.f - g) * (1.f + g);
            if (t == TT - 1) out_c[hb] = cy;
        }

        // ---- signal cells done ----
        __threadfence();
        __syncthreads();
        if (tid == 0) atomicAdd(&g_cnt_c[t][nt], 1u);
    }
}

// ---------------- reverse suffix-product scan ----------------
__global__ void scan_kernel(float* __restrict__ evb_out) {
    int idx = blockIdx.x * blockDim.x + threadIdx.x;  // < BB*H3
    int b = idx / H3, j = idx % H3;
    int h = j & (HH - 1);
    float p = 1.f, sum = 0.f;
    for (int t = TT - 1; t >= 0; t--) {
        size_t di = (size_t)t * BB * H3 + (size_t)b * H3 + j;
        float w = g_d[di] * p;
        g_d[di] = w;
        sum += w;
        p *= g_f[(size_t)t * BB * HH + (size_t)b * HH + h];
    }
    evb_out[idx] = sum;
}

// ---------------- batched ev GEMM: out[b][j][k] = sum_t w[t][b][j] * Xs[t][b][k] ----------------
// B-tile swizzled via PF4.
__global__ void ev_kernel(const float* __restrict__ Xs, int kdim, float* __restrict__ out) {
    __shared__ __align__(16) float Ws[8][128];
    __shared__ __align__(16) float Bs[8][140];    // 35 f4 slots
    if (Xs == nullptr) Xs = g_h;  // ev_hh: h_{t-1} history
    const int tid = threadIdx.x;
    const int b = blockIdx.z;
    const int j0 = blockIdx.y * 128;
    const int k0 = blockIdx.x * 128;
    const int tj = (tid >> 4) * 8, tk = (tid & 15) * 8;
    const int pk0 = PF4(tk >> 2);
    const int pk1 = PF4((tk >> 2) + 1);
    const int ltt = tid >> 5;
    const int lj = (tid & 31) * 4;
    float acc[8][8] = {};
    for (int t0 = 0; t0 < TT; t0 += 8) {
        int t = t0 + ltt;
        float4 wv = make_float4(0.f, 0.f, 0.f, 0.f);
        float4 xv = make_float4(0.f, 0.f, 0.f, 0.f);
        if (t < TT) {
            wv = *(const float4*)(g_d + (size_t)t * BB * H3 + (size_t)b * H3 + j0 + lj);
            xv = *(const float4*)(Xs + ((size_t)t * BB + b) * kdim + k0 + lj);
        }
        *(float4*)&Ws[ltt][lj] = wv;
        ((float4*)&Bs[ltt][0])[PF4(tid & 31)] = xv;
        __syncthreads();
#pragma unroll
        for (int u = 0; u < 8; u++) {
            float4 a0 = *(const float4*)&Ws[u][tj];
            float4 a1 = *(const float4*)&Ws[u][tj + 4];
            float4 b0 = ((const float4*)&Bs[u][0])[pk0];
            float4 b1 = ((const float4*)&Bs[u][0])[pk1];
            float aa[8] = {a0.x, a0.y, a0.z, a0.w, a1.x, a1.y, a1.z, a1.w};
            float bb[8] = {b0.x, b0.y, b0.z, b0.w, b1.x, b1.y, b1.z, b1.w};
#pragma unroll
            for (int i = 0; i < 8; i++)
#pragma unroll
                for (int j = 0; j < 8; j++)
                    acc[i][j] += aa[i] * bb[j];
        }
        __syncthreads();
    }
#pragma unroll
    for (int i = 0; i < 8; i++) {
        float* orow = out + ((size_t)b * H3 + j0 + tj + i) * kdim + k0 + tk;
        *(float4*)orow = make_float4(acc[i][0], acc[i][1], acc[i][2], acc[i][3]);
        *(float4*)(orow + 4) = make_float4(acc[i][4], acc[i][5], acc[i][6], acc[i][7]);
    }
}

// ---------------- launch ----------------
extern "C" void kernel_launch(void* const* d_in, const int* in_sizes, int n_in,
                              void* d_out, int out_size) {
    (void)in_sizes; (void)n_in; (void)out_size;
    const float* input = (const float*)d_in[0];
    const float* h0    = (const float*)d_in[1];
    const float* c0    = (const float*)d_in[2];
    const float* wih   = (const float*)d_in[3];
    const float* whh   = (const float*)d_in[4];
    const float* bih   = (const float*)d_in[5];
    const float* bhh   = (const float*)d_in[6];

    float* out         = (float*)d_out;
    float* out_outputs = out;
    float* out_cx      = out_outputs + (size_t)TT * BB * HH;
    float* out_evih    = out_cx + (size_t)BB * HH;
    float* out_evhh    = out_evih + (size_t)BB * H3 * II;
    float* out_evb     = out_evhh + (size_t)BB * H3 * HH;

    prep_kernel<<<512, 256>>>(h0, bih, bhh);
    pack_w<<<dim3(II / 32, H4 / 32), dim3(32, 8)>>>(wih, II, 0);
    pack_w<<<dim3(HH / 32, H4 / 32), dim3(32, 8)>>>(whh, HH, 1);
    gx_kernel<<<dim3(16, 50), 256>>>(input);

    loop_kernel<<<NBLK, 256>>>(c0, out_outputs, out_cx);

    scan_kernel<<<BB * H3 / 256, 256>>>(out_evb);
    ev_kernel<<<dim3(II / 128, H3 / 128, BB), 256>>>(input, II, out_evih);
    ev_kernel<<<dim3(HH / 128, H3 / 128, BB), 256>>>(nullptr, HH, out_evhh);
}